// round 1
// baseline (speedup 1.0000x reference)
#include <cuda_runtime.h>
#include <cuda_bf16.h>
#include <math.h>

// Problem constants: b=4, C=64, H=W=64, n=4096, C8=8, C16=4
#define B 4
#define C 64
#define N 4096           // h*w
#define CQ 8             // C/8 (Q/K dim)
#define NPIX (B * N)     // 16384

// Scratch (device globals: allocation-free rule)
__device__ float g_Q[B * N * CQ];     // [b][n][8], pre-scaled by 1/8
__device__ float g_K[B * N * CQ];     // [b][m][8]
__device__ float g_V[B * N * C];      // [b][m][64]
__device__ float g_gate[B * C];       // [b][64]

// ---------------------------------------------------------------------------
// Kernel 1: per-pixel 1x1 convs -> Q, K, V
// ---------------------------------------------------------------------------
__global__ void qkv_kernel(const float* __restrict__ x,
                           const float* __restrict__ Wq, const float* __restrict__ bq,
                           const float* __restrict__ Wk, const float* __restrict__ bk,
                           const float* __restrict__ Wv, const float* __restrict__ bv) {
    __shared__ float sWq[CQ * C], sWk[CQ * C], sWv[C * C];
    __shared__ float sbq[CQ], sbk[CQ], sbv[C];

    int t = threadIdx.x;  // 256 threads
    for (int i = t; i < CQ * C; i += 256) { sWq[i] = Wq[i]; sWk[i] = Wk[i]; }
    for (int i = t; i < C * C; i += 256) sWv[i] = Wv[i];
    if (t < CQ) { sbq[t] = bq[t]; sbk[t] = bk[t]; }
    if (t < C) sbv[t] = bv[t];
    __syncthreads();

    int g = blockIdx.x * 256 + t;       // global pixel id over b*n
    int b = g >> 12;
    int n = g & (N - 1);

    const float* xp = x + (size_t)b * C * N + n;
    float xv[C];
#pragma unroll
    for (int c = 0; c < C; c++) xv[c] = xp[c * N];

    float* Qp = g_Q + (size_t)g * CQ;
    float* Kp = g_K + (size_t)g * CQ;
#pragma unroll
    for (int o = 0; o < CQ; o++) {
        float aq = sbq[o], ak = sbk[o];
#pragma unroll
        for (int c = 0; c < C; c++) {
            aq = fmaf(sWq[o * C + c], xv[c], aq);
            ak = fmaf(sWk[o * C + c], xv[c], ak);
        }
        Qp[o] = aq * 0.125f;   // fold 1/sqrt(C) scale into Q
        Kp[o] = ak;
    }

    float* Vp = g_V + (size_t)g * C;
#pragma unroll
    for (int vo = 0; vo < C; vo += 8) {
        float a[8];
#pragma unroll
        for (int j = 0; j < 8; j++) a[j] = sbv[vo + j];
#pragma unroll
        for (int c = 0; c < C; c++) {
            float xc = xv[c];
#pragma unroll
            for (int j = 0; j < 8; j++) a[j] = fmaf(sWv[(vo + j) * C + c], xc, a[j]);
        }
#pragma unroll
        for (int j = 0; j < 8; j++) Vp[vo + j] = a[j];
    }
}

// ---------------------------------------------------------------------------
// Kernel 2: SE gate. One block per batch.
// ---------------------------------------------------------------------------
__global__ void gate_kernel(const float* __restrict__ x,
                            const float* __restrict__ W1, const float* __restrict__ b1,
                            const float* __restrict__ W2, const float* __restrict__ b2) {
    __shared__ float savg[C];
    __shared__ float shid[4];
    int b = blockIdx.x;
    int t = threadIdx.x;  // 256
    int lane = t & 31;

    if (t < C) savg[t] = 0.0f;
    __syncthreads();

    const float* xb = x + (size_t)b * C * N;
    // flat index j = t + 256*i covers [C*N); channel c = j >> 12, and for
    // i in [16k, 16k+16) all j fall in channel k exactly.
    for (int k = 0; k < C; k++) {
        float s = 0.0f;
#pragma unroll
        for (int ii = 0; ii < 16; ii++) s += xb[t + 256 * (16 * k + ii)];
#pragma unroll
        for (int off = 16; off > 0; off >>= 1)
            s += __shfl_down_sync(0xFFFFFFFFu, s, off);
        if (lane == 0) atomicAdd(&savg[k], s);
    }
    __syncthreads();

    if (t < 4) {
        float h = b1[t];
        for (int c = 0; c < C; c++) h = fmaf(W1[t * C + c], savg[c] * (1.0f / (float)N), h);
        shid[t] = fmaxf(h, 0.0f);
    }
    __syncthreads();

    if (t < C) {
        float gacc = b2[t];
#pragma unroll
        for (int j = 0; j < 4; j++) gacc = fmaf(W2[t * 4 + j], shid[j], gacc);
        g_gate[b * C + t] = 1.0f / (1.0f + __expf(-gacc));
    }
}

// ---------------------------------------------------------------------------
// Kernel 3: flash-attention (no-max softmax, exact since scores are O(1))
// 64 threads per CTA, one query per thread. grid = B * (N/64) = 256 CTAs.
// ---------------------------------------------------------------------------
#define TK 128   // key tile

__global__ void attn_kernel(float* __restrict__ out) {
    __shared__ __align__(16) float sK[TK * CQ];     // 4 KB
    __shared__ __align__(16) float sV[TK * C];      // 32 KB
    __shared__ float sGate[C];

    int b = blockIdx.x >> 6;        // 64 query blocks per batch
    int qb = blockIdx.x & 63;
    int tid = threadIdx.x;          // 64 threads
    int q = qb * 64 + tid;

    const float* Qp = g_Q + ((size_t)b * N + q) * CQ;
    float qr[CQ];
#pragma unroll
    for (int i = 0; i < CQ; i++) qr[i] = Qp[i];

    if (tid < C) sGate[tid] = g_gate[b * C + tid];

    float acc[C];
#pragma unroll
    for (int v = 0; v < C; v++) acc[v] = 0.0f;
    float ssum = 0.0f;

    for (int kt = 0; kt < N; kt += TK) {
        __syncthreads();
        const float4* Kg = (const float4*)(g_K + ((size_t)b * N + kt) * CQ);
        float4* sK4 = (float4*)sK;
#pragma unroll
        for (int i = tid; i < TK * CQ / 4; i += 64) sK4[i] = Kg[i];

        const float4* Vg = (const float4*)(g_V + ((size_t)b * N + kt) * C);
        float4* sV4 = (float4*)sV;
#pragma unroll 8
        for (int i = tid; i < TK * C / 4; i += 64) sV4[i] = Vg[i];
        __syncthreads();

#pragma unroll 2
        for (int m = 0; m < TK; m++) {
            const float4* Kr = (const float4*)&sK[m * CQ];
            float4 k0 = Kr[0], k1 = Kr[1];
            float s = qr[0] * k0.x + qr[1] * k0.y + qr[2] * k0.z + qr[3] * k0.w
                    + qr[4] * k1.x + qr[5] * k1.y + qr[6] * k1.z + qr[7] * k1.w;
            float p = __expf(s);     // Q pre-scaled by 1/8; scores O(1): no max needed
            ssum += p;
            const float4* Vr = (const float4*)&sV[m * C];
#pragma unroll
            for (int j = 0; j < C / 4; j++) {
                float4 vv = Vr[j];
                acc[4 * j + 0] = fmaf(p, vv.x, acc[4 * j + 0]);
                acc[4 * j + 1] = fmaf(p, vv.y, acc[4 * j + 1]);
                acc[4 * j + 2] = fmaf(p, vv.z, acc[4 * j + 2]);
                acc[4 * j + 3] = fmaf(p, vv.w, acc[4 * j + 3]);
            }
        }
    }

    float inv = 1.0f / ssum;
    float* op = out + (size_t)b * C * N + q;
#pragma unroll
    for (int v = 0; v < C; v++) op[v * N] = acc[v] * sGate[v] * inv;
}

// ---------------------------------------------------------------------------
extern "C" void kernel_launch(void* const* d_in, const int* in_sizes, int n_in,
                              void* d_out, int out_size) {
    const float* x  = (const float*)d_in[0];
    const float* Wq = (const float*)d_in[1];
    const float* bq = (const float*)d_in[2];
    const float* Wk = (const float*)d_in[3];
    const float* bk = (const float*)d_in[4];
    const float* Wv = (const float*)d_in[5];
    const float* bv = (const float*)d_in[6];
    const float* W1 = (const float*)d_in[7];
    const float* b1 = (const float*)d_in[8];
    const float* W2 = (const float*)d_in[9];
    const float* b2 = (const float*)d_in[10];
    float* out = (float*)d_out;

    qkv_kernel<<<NPIX / 256, 256>>>(x, Wq, bq, Wk, bk, Wv, bv);
    gate_kernel<<<B, 256>>>(x, W1, b1, W2, b2);
    attn_kernel<<<B * (N / 64), 64>>>(out);
}

// round 3
// speedup vs baseline: 4.7649x; 4.7649x over previous
#include <cuda_runtime.h>
#include <cuda_bf16.h>
#include <cstdint>
#include <math.h>

// Problem constants
#define B 4
#define C 64
#define N 4096
#define NT 32            // key tiles of 128

// ---------------------------------------------------------------------------
// Scratch (device globals, allocation-free rule)
// ---------------------------------------------------------------------------
__device__ __align__(16) __nv_bfloat16 g_Qb[B * N * 8];   // [b][n][8], pre-scaled 1/8
__device__ __align__(16) __nv_bfloat16 g_Kb[B * N * 8];   // [b][m][8]
__device__ __align__(16) __nv_bfloat16 g_Vt[B * C * N];   // [b][ch][m]  (transposed)
__device__ float g_gate[B * C];

// ---------------------------------------------------------------------------
// Helpers
// ---------------------------------------------------------------------------
__device__ __forceinline__ uint32_t smem_u32(const void* p) {
    uint32_t a;
    asm("{ .reg .u64 t; cvta.to.shared.u64 t, %1; cvt.u32.u64 %0, t; }" : "=r"(a) : "l"(p));
    return a;
}

// pack two f32 -> bf16x2: lo = a, hi = b
#define CVT2(r, a, b) \
    asm("cvt.rn.satfinite.bf16x2.f32 %0, %1, %2;" : "=r"(r) : "f"(b), "f"(a))

#define CP_ASYNC16(dst, src) \
    asm volatile("cp.async.cg.shared.global [%0], [%1], 16;" :: "r"(dst), "l"(src) : "memory")
#define CP_COMMIT() asm volatile("cp.async.commit_group;" ::: "memory")
#define CP_WAIT0()  asm volatile("cp.async.wait_group 0;" ::: "memory")

#define LDS32(r, a) asm volatile("ld.shared.b32 %0, [%1];" : "=r"(r) : "r"(a))

// S[16x8] += Q[16x8] * K^T ;  A = 2 regs, B = 1 reg
__device__ __forceinline__ void mma_k8(float& c0, float& c1, float& c2, float& c3,
                                       uint32_t a0, uint32_t a1, uint32_t b0) {
    asm volatile(
        "mma.sync.aligned.m16n8k8.row.col.f32.bf16.bf16.f32 "
        "{%0,%1,%2,%3}, {%4,%5}, {%6}, {%0,%1,%2,%3};"
        : "+f"(c0), "+f"(c1), "+f"(c2), "+f"(c3)
        : "r"(a0), "r"(a1), "r"(b0));
}
// O[16x8] += P[16x16] * V ;  A = 4 regs, B = 2 regs
__device__ __forceinline__ void mma_k16(float* c, uint32_t a0, uint32_t a1,
                                        uint32_t a2, uint32_t a3,
                                        uint32_t b0, uint32_t b1) {
    asm volatile(
        "mma.sync.aligned.m16n8k16.row.col.f32.bf16.bf16.f32 "
        "{%0,%1,%2,%3}, {%4,%5,%6,%7}, {%8,%9}, {%0,%1,%2,%3};"
        : "+f"(c[0]), "+f"(c[1]), "+f"(c[2]), "+f"(c[3])
        : "r"(a0), "r"(a1), "r"(a2), "r"(a3), "r"(b0), "r"(b1));
}

// ---------------------------------------------------------------------------
// Kernel 1: QKV projections -> bf16 scratch (Q pre-scaled 1/8, V transposed)
// grid 256 x 128; warps 0-1: Q,K,V[0:24); warps 2-3: V[24:64)
// ---------------------------------------------------------------------------
__global__ void __launch_bounds__(128) qkv_kernel(
    const float* __restrict__ x,
    const float* __restrict__ Wq, const float* __restrict__ bq,
    const float* __restrict__ Wk, const float* __restrict__ bk,
    const float* __restrict__ Wv, const float* __restrict__ bv) {
    __shared__ float sWq[8 * C], sWk[8 * C], sWv[C * C];
    __shared__ float sbq[8], sbk[8], sbv[C];
    int t = threadIdx.x;
    for (int i = t; i < 8 * C; i += 128) { sWq[i] = Wq[i]; sWk[i] = Wk[i]; }
    for (int i = t; i < C * C; i += 128) sWv[i] = Wv[i];
    if (t < 8) { sbq[t] = bq[t]; sbk[t] = bk[t]; }
    if (t < C) sbv[t] = bv[t];
    __syncthreads();

    int half = t >> 6;
    int pix = blockIdx.x * 64 + (t & 63);
    int bb = pix >> 12, n = pix & (N - 1);
    const float* xp = x + (size_t)bb * C * N + n;

    if (half == 0) {
        float qa[8], ka[8], va[24];
#pragma unroll
        for (int o = 0; o < 8; o++) { qa[o] = sbq[o]; ka[o] = sbk[o]; }
#pragma unroll
        for (int v = 0; v < 24; v++) va[v] = sbv[v];
        for (int c0 = 0; c0 < C; c0 += 16) {
            float xv[16];
#pragma unroll
            for (int j = 0; j < 16; j++) xv[j] = xp[(size_t)(c0 + j) * N];
#pragma unroll
            for (int j = 0; j < 16; j++) {
                float xc = xv[j]; int c = c0 + j;
#pragma unroll
                for (int o = 0; o < 8; o++) {
                    qa[o] = fmaf(sWq[o * C + c], xc, qa[o]);
                    ka[o] = fmaf(sWk[o * C + c], xc, ka[o]);
                }
#pragma unroll
                for (int v = 0; v < 24; v++) va[v] = fmaf(sWv[v * C + c], xc, va[v]);
            }
        }
        uint32_t w[4], u[4];
#pragma unroll
        for (int j = 0; j < 4; j++) {
            CVT2(w[j], qa[2 * j] * 0.125f, qa[2 * j + 1] * 0.125f);
            CVT2(u[j], ka[2 * j], ka[2 * j + 1]);
        }
        *(uint4*)(g_Qb + (size_t)pix * 8) = make_uint4(w[0], w[1], w[2], w[3]);
        *(uint4*)(g_Kb + (size_t)pix * 8) = make_uint4(u[0], u[1], u[2], u[3]);
#pragma unroll
        for (int v = 0; v < 24; v++)
            g_Vt[((size_t)bb * C + v) * N + n] = __float2bfloat16(va[v]);
    } else {
        float va[40];
#pragma unroll
        for (int v = 0; v < 40; v++) va[v] = sbv[24 + v];
        for (int c0 = 0; c0 < C; c0 += 16) {
            float xv[16];
#pragma unroll
            for (int j = 0; j < 16; j++) xv[j] = xp[(size_t)(c0 + j) * N];
#pragma unroll
            for (int j = 0; j < 16; j++) {
                float xc = xv[j]; int c = c0 + j;
#pragma unroll
                for (int v = 0; v < 40; v++) va[v] = fmaf(sWv[(24 + v) * C + c], xc, va[v]);
            }
        }
#pragma unroll
        for (int v = 0; v < 40; v++)
            g_Vt[((size_t)bb * C + 24 + v) * N + n] = __float2bfloat16(va[v]);
    }
}

// ---------------------------------------------------------------------------
// Kernel 2: SE gate
// ---------------------------------------------------------------------------
__global__ void gate_kernel(const float* __restrict__ x,
                            const float* __restrict__ W1, const float* __restrict__ b1,
                            const float* __restrict__ W2, const float* __restrict__ b2) {
    __shared__ float savg[C];
    __shared__ float shid[4];
    int b = blockIdx.x;
    int t = threadIdx.x;
    int lane = t & 31;
    if (t < C) savg[t] = 0.0f;
    __syncthreads();
    const float* xb = x + (size_t)b * C * N;
    for (int k = 0; k < C; k++) {
        float s = 0.0f;
#pragma unroll
        for (int ii = 0; ii < 16; ii++) s += xb[t + 256 * (16 * k + ii)];
#pragma unroll
        for (int off = 16; off > 0; off >>= 1) s += __shfl_down_sync(0xFFFFFFFFu, s, off);
        if (lane == 0) atomicAdd(&savg[k], s);
    }
    __syncthreads();
    if (t < 4) {
        float h = b1[t];
        for (int c = 0; c < C; c++) h = fmaf(W1[t * C + c], savg[c] * (1.0f / (float)N), h);
        shid[t] = fmaxf(h, 0.0f);
    }
    __syncthreads();
    if (t < C) {
        float gacc = b2[t];
#pragma unroll
        for (int j = 0; j < 4; j++) gacc = fmaf(W2[t * 4 + j], shid[j], gacc);
        g_gate[b * C + t] = 1.0f / (1.0f + __expf(-gacc));
    }
}

// ---------------------------------------------------------------------------
// Kernel 3: HMMA flash attention.
// grid = B*64 CTAs x 128 threads (4 warps, 16 queries/warp, 64 q/CTA).
// Double-buffered K (2KB) + V-transposed (17408B, row stride 272B) via cp.async.
// ---------------------------------------------------------------------------
#define VROW 136   // halfwords per V smem row (272 B): bank-conflict-free

__global__ void __launch_bounds__(128, 2) attn_kernel(float* __restrict__ out) {
    __shared__ __align__(16) __nv_bfloat16 sK[2][128 * 8];
    __shared__ __align__(16) __nv_bfloat16 sV[2][64 * VROW];
    __shared__ float sGate[C];

    int tid = threadIdx.x, w = tid >> 5, lane = tid & 31;
    int g = lane >> 2, t = lane & 3;
    int bb = blockIdx.x >> 6, qb = blockIdx.x & 63;
    int q0 = qb * 64 + w * 16;

    if (tid < C) sGate[tid] = g_gate[bb * C + tid];

    // Q fragments (m16n8k8 A): a0 = Q[q0+g][2t..2t+1], a1 = Q[q0+8+g][..]
    const __nv_bfloat16* Qp = g_Qb + ((size_t)bb * N + q0) * 8;
    uint32_t qa0 = *(const uint32_t*)(Qp + (size_t)g * 8 + t * 2);
    uint32_t qa1 = *(const uint32_t*)(Qp + (size_t)(g + 8) * 8 + t * 2);

    uint32_t skb = smem_u32(sK), svb = smem_u32(sV);

    // cp.async staging map: thread -> (ch, half) for V; flat for K
    int ch_cp = tid >> 1, half_cp = tid & 1;
    const char* ksrc0 = (const char*)(g_Kb + (size_t)bb * N * 8) + tid * 16;
    const char* vsrc0 = (const char*)(g_Vt + ((size_t)bb * C + ch_cp) * N + half_cp * 64);
    uint32_t kdst = skb + tid * 16;
    uint32_t vdst = svb + ch_cp * (VROW * 2) + half_cp * 128;

    // prologue: tile 0
    CP_ASYNC16(kdst, ksrc0);
#pragma unroll
    for (int c = 0; c < 8; c++) CP_ASYNC16(vdst + c * 16, vsrc0 + c * 16);
    CP_COMMIT();

    float o[8][4] = {};
    float sum0 = 0.0f, sum1 = 0.0f;
    const uint32_t kfb = skb + g * 16 + t * 4;        // K B-frag base
    const uint32_t vfb = svb + g * (VROW * 2) + t * 4; // V B-frag base

#pragma unroll 1
    for (int kt = 0; kt < NT; kt++) {
        int cur = kt & 1;
        CP_WAIT0();
        __syncthreads();
        if (kt + 1 < NT) {
            int nx = (kt + 1) & 1;
            const char* ks = ksrc0 + (size_t)(kt + 1) * 2048;
            const char* vs = vsrc0 + (size_t)(kt + 1) * 256;
            CP_ASYNC16(kdst + nx * 2048, ks);
#pragma unroll
            for (int c = 0; c < 8; c++)
                CP_ASYNC16(vdst + nx * (64 * VROW * 2) + c * 16, vs + c * 16);
            CP_COMMIT();
        }
        uint32_t kb = kfb + cur * 2048;
        uint32_t vb = vfb + cur * (64 * VROW * 2);
#pragma unroll
        for (int nt2 = 0; nt2 < 8; nt2++) {
            uint32_t kk0, kk1;
            LDS32(kk0, kb + nt2 * 256);
            LDS32(kk1, kb + nt2 * 256 + 128);
            float c0 = 0, c1 = 0, c2 = 0, c3 = 0, c4 = 0, c5 = 0, c6 = 0, c7 = 0;
            mma_k8(c0, c1, c2, c3, qa0, qa1, kk0);   // keys nt2*16 + 0..7
            mma_k8(c4, c5, c6, c7, qa0, qa1, kk1);   // keys nt2*16 + 8..15
            float p0 = __expf(c0), p1 = __expf(c1), p2 = __expf(c2), p3 = __expf(c3);
            float p4 = __expf(c4), p5 = __expf(c5), p6 = __expf(c6), p7 = __expf(c7);
            sum0 += p0 + p1 + p4 + p5;   // row g
            sum1 += p2 + p3 + p6 + p7;   // row g+8
            uint32_t a0, a1, a2, a3;     // P as m16n8k16 A fragment
            CVT2(a0, p0, p1);
            CVT2(a1, p2, p3);
            CVT2(a2, p4, p5);
            CVT2(a3, p6, p7);
#pragma unroll
            for (int ct = 0; ct < 8; ct++) {
                uint32_t b0, b1;
                LDS32(b0, vb + ct * (8 * VROW * 2) + nt2 * 32);
                LDS32(b1, vb + ct * (8 * VROW * 2) + nt2 * 32 + 16);
                mma_k16(o[ct], a0, a1, a2, a3, b0, b1);
            }
        }
    }

    // row-sum reduce across the 4 lanes of each row group (adjacent lanes)
    sum0 += __shfl_xor_sync(0xFFFFFFFFu, sum0, 1);
    sum0 += __shfl_xor_sync(0xFFFFFFFFu, sum0, 2);
    sum1 += __shfl_xor_sync(0xFFFFFFFFu, sum1, 1);
    sum1 += __shfl_xor_sync(0xFFFFFFFFu, sum1, 2);
    float inv0 = 1.0f / sum0, inv1 = 1.0f / sum1;

    int r0 = q0 + g, r1 = q0 + 8 + g;
    float* outb = out + (size_t)bb * C * N;
#pragma unroll
    for (int ct = 0; ct < 8; ct++) {
        int ch0 = ct * 8 + t * 2;
        float gA = sGate[ch0], gB = sGate[ch0 + 1];
        outb[(size_t)ch0 * N + r0]       = o[ct][0] * inv0 * gA;
        outb[(size_t)(ch0 + 1) * N + r0] = o[ct][1] * inv0 * gB;
        outb[(size_t)ch0 * N + r1]       = o[ct][2] * inv1 * gA;
        outb[(size_t)(ch0 + 1) * N + r1] = o[ct][3] * inv1 * gB;
    }
}

// ---------------------------------------------------------------------------
extern "C" void kernel_launch(void* const* d_in, const int* in_sizes, int n_in,
                              void* d_out, int out_size) {
    const float* x  = (const float*)d_in[0];
    const float* Wq = (const float*)d_in[1];
    const float* bq = (const float*)d_in[2];
    const float* Wk = (const float*)d_in[3];
    const float* bk = (const float*)d_in[4];
    const float* Wv = (const float*)d_in[5];
    const float* bv = (const float*)d_in[6];
    const float* W1 = (const float*)d_in[7];
    const float* b1 = (const float*)d_in[8];
    const float* W2 = (const float*)d_in[9];
    const float* b2 = (const float*)d_in[10];
    float* out = (float*)d_out;

    qkv_kernel<<<256, 128>>>(x, Wq, bq, Wk, bk, Wv, bv);
    gate_kernel<<<B, 256>>>(x, W1, b1, W2, b2);
    attn_kernel<<<B * 64, 128>>>(out);
}

// round 5
// speedup vs baseline: 8.8085x; 1.8486x over previous
#include <cuda_runtime.h>
#include <cuda_bf16.h>
#include <cstdint>
#include <math.h>

#define B 4
#define C 64
#define N 4096

// ---------------------------------------------------------------------------
// Scratch (device globals, allocation-free rule)
// ---------------------------------------------------------------------------
__device__ __align__(16) __nv_bfloat16 g_Qb[B * N * 8];   // [b][n][8], scaled 0.125*log2e
__device__ __align__(16) __nv_bfloat16 g_Kb[B * N * 8];   // [b][m][8]
__device__ __align__(16) __nv_bfloat16 g_Vt[B * C * N];   // [b][ch][m] transposed
__device__ float g_gate[B * C];
__device__ float g_avg[B * C];

// ---------------------------------------------------------------------------
// Helpers
// ---------------------------------------------------------------------------
__device__ __forceinline__ uint32_t smem_u32(const void* p) {
    uint32_t a;
    asm("{ .reg .u64 t; cvta.to.shared.u64 t, %1; cvt.u32.u64 %0, t; }" : "=r"(a) : "l"(p));
    return a;
}
__device__ __forceinline__ float ex2f(float x) {
    float r;
    asm("ex2.approx.ftz.f32 %0, %1;" : "=f"(r) : "f"(x));
    return r;
}
#define CVT2(r, a, b) \
    asm("cvt.rn.satfinite.bf16x2.f32 %0, %1, %2;" : "=r"(r) : "f"(b), "f"(a))
#define CP_ASYNC16(dst, src) \
    asm volatile("cp.async.cg.shared.global [%0], [%1], 16;" :: "r"(dst), "l"(src) : "memory")
#define CP_COMMIT() asm volatile("cp.async.commit_group;" ::: "memory")
#define CP_WAIT0()  asm volatile("cp.async.wait_group 0;" ::: "memory")

#define LDSM_X2(r0, r1, a) \
    asm volatile("ldmatrix.sync.aligned.m8n8.x2.shared.b16 {%0,%1}, [%2];" \
                 : "=r"(r0), "=r"(r1) : "r"(a))
#define LDSM_X4(r0, r1, r2, r3, a) \
    asm volatile("ldmatrix.sync.aligned.m8n8.x4.shared.b16 {%0,%1,%2,%3}, [%4];" \
                 : "=r"(r0), "=r"(r1), "=r"(r2), "=r"(r3) : "r"(a))

__device__ __forceinline__ void mma_k8(float& c0, float& c1, float& c2, float& c3,
                                       uint32_t a0, uint32_t a1, uint32_t b0) {
    asm volatile(
        "mma.sync.aligned.m16n8k8.row.col.f32.bf16.bf16.f32 "
        "{%0,%1,%2,%3}, {%4,%5}, {%6}, {%0,%1,%2,%3};"
        : "+f"(c0), "+f"(c1), "+f"(c2), "+f"(c3)
        : "r"(a0), "r"(a1), "r"(b0));
}
__device__ __forceinline__ void mma_k16(float* c, const uint32_t* a,
                                        uint32_t b0, uint32_t b1) {
    asm volatile(
        "mma.sync.aligned.m16n8k16.row.col.f32.bf16.bf16.f32 "
        "{%0,%1,%2,%3}, {%4,%5,%6,%7}, {%8,%9}, {%0,%1,%2,%3};"
        : "+f"(c[0]), "+f"(c[1]), "+f"(c[2]), "+f"(c[3])
        : "r"(a[0]), "r"(a[1]), "r"(a[2]), "r"(a[3]), "r"(b0), "r"(b1));
}

// exp(s/8) = 2^(s * 0.125*log2e); scale folded into Q
#define QSCALE (0.125f * 1.4426950408889634f)

// ---------------------------------------------------------------------------
// Kernel 1: QKV projections. 256 CTAs x 128 thr, 64 pixels/CTA.
// x tile staged via smem (coalesced); 2 threads/pixel output-split.
// ---------------------------------------------------------------------------
__global__ void __launch_bounds__(128) qkv_kernel(
    const float* __restrict__ x,
    const float* __restrict__ Wq, const float* __restrict__ bq,
    const float* __restrict__ Wk, const float* __restrict__ bk,
    const float* __restrict__ Wv, const float* __restrict__ bv) {
    __shared__ float sX[C * 64];                 // [c][px] 16KB
    __shared__ float sWq[8 * C], sWk[8 * C], sWv[C * C];
    __shared__ float sbq[8], sbk[8], sbv[C];

    int t = threadIdx.x;
    for (int i = t; i < 8 * C; i += 128) { sWq[i] = Wq[i]; sWk[i] = Wk[i]; }
    for (int i = t; i < C * C; i += 128) sWv[i] = Wv[i];
    if (t < 8) { sbq[t] = bq[t]; sbk[t] = bk[t]; }
    if (t < C) sbv[t] = bv[t];

    int pix0 = blockIdx.x * 64;
    int bb = pix0 >> 12, n0 = pix0 & (N - 1);
    // stage x tile: 64 ch x 64 px, float4 coalesced
    {
        const float4* xs = (const float4*)(x + (size_t)bb * C * N + n0);
        float4* xd = (float4*)sX;
#pragma unroll
        for (int j = 0; j < 8; j++) {
            int id = t + 128 * j;           // 1024 float4
            int row = id >> 4, col = id & 15;
            xd[row * 16 + col] = xs[(size_t)row * (N / 4) + col];
        }
    }
    __syncthreads();

    int half = t >> 6, px = t & 63;
    int pix = pix0 + px, n = n0 + px;

    if (half == 0) {
        float qa[8], ka[8], va[24];
#pragma unroll
        for (int o = 0; o < 8; o++) { qa[o] = sbq[o]; ka[o] = sbk[o]; }
#pragma unroll
        for (int v = 0; v < 24; v++) va[v] = sbv[v];
#pragma unroll 4
        for (int c = 0; c < C; c++) {
            float xc = sX[c * 64 + px];
#pragma unroll
            for (int o = 0; o < 8; o++) {
                qa[o] = fmaf(sWq[o * C + c], xc, qa[o]);
                ka[o] = fmaf(sWk[o * C + c], xc, ka[o]);
            }
#pragma unroll
            for (int v = 0; v < 24; v++) va[v] = fmaf(sWv[v * C + c], xc, va[v]);
        }
        uint32_t w[4], u[4];
#pragma unroll
        for (int j = 0; j < 4; j++) {
            CVT2(w[j], qa[2 * j] * QSCALE, qa[2 * j + 1] * QSCALE);
            CVT2(u[j], ka[2 * j], ka[2 * j + 1]);
        }
        *(uint4*)(g_Qb + (size_t)pix * 8) = make_uint4(w[0], w[1], w[2], w[3]);
        *(uint4*)(g_Kb + (size_t)pix * 8) = make_uint4(u[0], u[1], u[2], u[3]);
#pragma unroll
        for (int v = 0; v < 24; v++)
            g_Vt[((size_t)bb * C + v) * N + n] = __float2bfloat16(va[v]);
    } else {
        float va[40];
#pragma unroll
        for (int v = 0; v < 40; v++) va[v] = sbv[24 + v];
#pragma unroll 4
        for (int c = 0; c < C; c++) {
            float xc = sX[c * 64 + px];
#pragma unroll
            for (int v = 0; v < 40; v++) va[v] = fmaf(sWv[(24 + v) * C + c], xc, va[v]);
        }
#pragma unroll
        for (int v = 0; v < 40; v++)
            g_Vt[((size_t)bb * C + 24 + v) * N + n] = __float2bfloat16(va[v]);
    }
}

// ---------------------------------------------------------------------------
// Kernel 2a: per-(batch,channel) sums. 256 CTAs x 128 thr.
// ---------------------------------------------------------------------------
__global__ void __launch_bounds__(128) gate_sum_kernel(const float* __restrict__ x) {
    __shared__ float wsum[4];
    int id = blockIdx.x;                   // b*64 + ch
    int t = threadIdx.x, lane = t & 31, w = t >> 5;
    const float4* p = (const float4*)(x + (size_t)id * N);
    float s = 0.0f;
#pragma unroll
    for (int j = 0; j < 8; j++) {
        float4 v = p[t + 128 * j];
        s += (v.x + v.y) + (v.z + v.w);
    }
#pragma unroll
    for (int off = 16; off > 0; off >>= 1) s += __shfl_down_sync(0xFFFFFFFFu, s, off);
    if (lane == 0) wsum[w] = s;
    __syncthreads();
    if (t == 0) g_avg[id] = (wsum[0] + wsum[1] + wsum[2] + wsum[3]) * (1.0f / (float)N);
}

// Kernel 2b: tiny MLP -> sigmoid gate. 4 blocks x 64 thr.
__global__ void gate_mlp_kernel(const float* __restrict__ W1, const float* __restrict__ b1,
                                const float* __restrict__ W2, const float* __restrict__ b2) {
    __shared__ float shid[4];
    int b = blockIdx.x, t = threadIdx.x;
    if (t < 4) {
        float h = b1[t];
#pragma unroll
        for (int c = 0; c < C; c++) h = fmaf(W1[t * C + c], g_avg[b * C + c], h);
        shid[t] = fmaxf(h, 0.0f);
    }
    __syncthreads();
    float g = b2[t];
#pragma unroll
    for (int j = 0; j < 4; j++) g = fmaf(W2[t * 4 + j], shid[j], g);
    g_gate[b * C + t] = 1.0f / (1.0f + __expf(-g));
}

// ---------------------------------------------------------------------------
// Kernel 3: HMMA flash attention, 32 q/warp, ldmatrix frags, split-K x2.
// 256 CTAs x 128 thr. Warp w: qgroup = w&1 (32 q), khalf = w>>1 (2048 keys).
// Dynamic smem: gate 256B | K [2kh][2buf][128x16B] | V [2kh][2buf][64x272B]
// Reduction overlays the V region after the main loop.
// ---------------------------------------------------------------------------
#define OFF_GATE 0
#define OFF_K    256
#define OFF_V    (256 + 8192)
#define SMEM_ATTN (256 + 8192 + 4 * 17408)
#define VPITCH 272          // bytes per V smem row (128 keys*2B + 16B pad)
#define REDP 66             // floats per reduction row (pad for banks)

__global__ void __launch_bounds__(128, 2) attn_kernel(float* __restrict__ out) {
    extern __shared__ char dsm[];
    uint32_t sb = smem_u32(dsm);
    int tid = threadIdx.x, w = tid >> 5, lane = tid & 31;
    int g = lane >> 2, t4 = lane & 3;
    int qg = w & 1, kh = w >> 1;
    int bb = blockIdx.x >> 6, qb = blockIdx.x & 63;
    int q0 = qb * 64 + qg * 32;

    if (tid < C) ((float*)(dsm + OFF_GATE))[tid] = g_gate[bb * C + tid];

    // Q fragments: rows q0+g, q0+8+g, q0+16+g, q0+24+g
    uint32_t qa[4];
    {
        const __nv_bfloat16* Qp = g_Qb + ((size_t)bb * N + q0) * 8 + t4 * 2;
#pragma unroll
        for (int r = 0; r < 4; r++)
            qa[r] = *(const uint32_t*)(Qp + (size_t)(r * 8 + g) * 8);
    }

    // --- staging setup (all threads stage both key-halves) ---
    const char* kgb = (const char*)(g_Kb + (size_t)bb * N * 8);
    const char* vgb = (const char*)(g_Vt + (size_t)bb * C * N);

    // --- fragment address bases (warp-local key half) ---
    uint32_t kfb = sb + OFF_K + kh * 4096 + (lane & 15) * 16;
    int vg2 = lane >> 3, vr = lane & 7;
    uint32_t vfb = sb + OFF_V + kh * 34816
                 + (uint32_t)(((vg2 >> 1) * 8 + vr) * VPITCH + (vg2 & 1) * 16);

    // prologue: stage tile 0 of both halves into buf 0
#pragma unroll
    for (int h = 0; h < 2; h++) {
        int key0 = h * 2048;
        CP_ASYNC16(sb + OFF_K + h * 4096 + tid * 16, kgb + (size_t)key0 * 16 + tid * 16);
#pragma unroll
        for (int j = 0; j < 8; j++) {
            int id = tid + 128 * j, row = id >> 4, c16 = id & 15;
            CP_ASYNC16(sb + OFF_V + h * 34816 + row * VPITCH + c16 * 16,
                       vgb + ((size_t)row * N + key0) * 2 + c16 * 16);
        }
    }
    CP_COMMIT();

    float o[2][8][4] = {};
    float sums[4] = {0.f, 0.f, 0.f, 0.f};

#pragma unroll 1
    for (int kt = 0; kt < 16; kt++) {
        int buf = kt & 1;
        CP_WAIT0();
        __syncthreads();
        if (kt + 1 < 16) {
            int nb = (kt + 1) & 1;
#pragma unroll
            for (int h = 0; h < 2; h++) {
                int key0 = h * 2048 + (kt + 1) * 128;
                CP_ASYNC16(sb + OFF_K + (h * 2 + nb) * 2048 + tid * 16,
                           kgb + (size_t)key0 * 16 + tid * 16);
#pragma unroll
                for (int j = 0; j < 8; j++) {
                    int id = tid + 128 * j, row = id >> 4, c16 = id & 15;
                    CP_ASYNC16(sb + OFF_V + (h * 2 + nb) * 17408 + row * VPITCH + c16 * 16,
                               vgb + ((size_t)row * N + key0) * 2 + c16 * 16);
                }
            }
            CP_COMMIT();
        }
        uint32_t ka = kfb + buf * 2048;
        uint32_t va = vfb + buf * 17408;
#pragma unroll
        for (int nt2 = 0; nt2 < 8; nt2++) {
            uint32_t kk0, kk1;
            LDSM_X2(kk0, kk1, ka + nt2 * 256);
            uint32_t a[2][4];
#pragma unroll
            for (int blk = 0; blk < 2; blk++) {
                float c0 = 0, c1 = 0, c2 = 0, c3 = 0, c4 = 0, c5 = 0, c6 = 0, c7 = 0;
                mma_k8(c0, c1, c2, c3, qa[2 * blk], qa[2 * blk + 1], kk0);
                mma_k8(c4, c5, c6, c7, qa[2 * blk], qa[2 * blk + 1], kk1);
                float p0 = ex2f(c0), p1 = ex2f(c1), p2 = ex2f(c2), p3 = ex2f(c3);
                float p4 = ex2f(c4), p5 = ex2f(c5), p6 = ex2f(c6), p7 = ex2f(c7);
                sums[2 * blk]     += (p0 + p1) + (p4 + p5);
                sums[2 * blk + 1] += (p2 + p3) + (p6 + p7);
                CVT2(a[blk][0], p0, p1);
                CVT2(a[blk][1], p2, p3);
                CVT2(a[blk][2], p4, p5);
                CVT2(a[blk][3], p6, p7);
            }
#pragma unroll
            for (int cp = 0; cp < 4; cp++) {
                uint32_t b0, b1, b2, b3;
                LDSM_X4(b0, b1, b2, b3, va + cp * (16 * VPITCH) + nt2 * 32);
                mma_k16(o[0][2 * cp], a[0], b0, b1);
                mma_k16(o[1][2 * cp], a[1], b0, b1);
                mma_k16(o[0][2 * cp + 1], a[0], b2, b3);
                mma_k16(o[1][2 * cp + 1], a[1], b2, b3);
            }
        }
    }

    // reduce sums across the 4 lanes of each row group
#pragma unroll
    for (int j = 0; j < 4; j++) {
        sums[j] += __shfl_xor_sync(0xFFFFFFFFu, sums[j], 1);
        sums[j] += __shfl_xor_sync(0xFFFFFFFFu, sums[j], 2);
    }

    __syncthreads();   // all warps done reading V smem; safe to overlay
    float* red = (float*)(dsm + OFF_V) + qg * (32 * REDP);
    float* reds = (float*)(dsm + OFF_V + 2 * 32 * REDP * 4);   // [2][32]

    if (kh == 1) {
#pragma unroll
        for (int blk = 0; blk < 2; blk++)
#pragma unroll
            for (int ct = 0; ct < 8; ct++) {
#pragma unroll
                for (int i = 0; i < 4; i++) {
                    int row = blk * 16 + g + (i >> 1) * 8;
                    red[row * REDP + ct * 8 + t4 * 2 + (i & 1)] = o[blk][ct][i];
                }
            }
        if (t4 == 0) {
#pragma unroll
            for (int j = 0; j < 4; j++)
                reds[qg * 32 + ((j >> 1) * 16 + (j & 1) * 8) + g] = sums[j];
        }
    }
    __syncthreads();
    if (kh == 0) {
        float inv[4];
#pragma unroll
        for (int j = 0; j < 4; j++) {
            int row = (j >> 1) * 16 + (j & 1) * 8 + g;
            inv[j] = 1.0f / (sums[j] + reds[qg * 32 + row]);
        }
        const float* gt = (const float*)(dsm + OFF_GATE);
        float* outb = out + (size_t)bb * C * N;
#pragma unroll
        for (int blk = 0; blk < 2; blk++)
#pragma unroll
            for (int ct = 0; ct < 8; ct++) {
#pragma unroll
                for (int i = 0; i < 4; i++) {
                    int row = blk * 16 + g + (i >> 1) * 8;
                    int ch = ct * 8 + t4 * 2 + (i & 1);
                    float v = o[blk][ct][i] + red[row * REDP + ch];
                    outb[(size_t)ch * N + q0 + row] = v * inv[2 * blk + (i >> 1)] * gt[ch];
                }
            }
    }
}

// ---------------------------------------------------------------------------
extern "C" void kernel_launch(void* const* d_in, const int* in_sizes, int n_in,
                              void* d_out, int out_size) {
    const float* x  = (const float*)d_in[0];
    const float* Wq = (const float*)d_in[1];
    const float* bq = (const float*)d_in[2];
    const float* Wk = (const float*)d_in[3];
    const float* bk = (const float*)d_in[4];
    const float* Wv = (const float*)d_in[5];
    const float* bv = (const float*)d_in[6];
    const float* W1 = (const float*)d_in[7];
    const float* b1 = (const float*)d_in[8];
    const float* W2 = (const float*)d_in[9];
    const float* b2 = (const float*)d_in[10];
    float* out = (float*)d_out;

    static int smem_set = 0;
    if (!smem_set) {
        cudaFuncSetAttribute(attn_kernel, cudaFuncAttributeMaxDynamicSharedMemorySize, SMEM_ATTN);
        smem_set = 1;
    }

    qkv_kernel<<<256, 128>>>(x, Wq, bq, Wk, bk, Wv, bv);
    gate_sum_kernel<<<256, 128>>>(x);
    gate_mlp_kernel<<<B, C>>>(W1, b1, W2, b2);
    attn_kernel<<<B * 64, 128, SMEM_ATTN>>>(out);
}